// round 1
// baseline (speedup 1.0000x reference)
#include <cuda_runtime.h>
#include <cstdint>

// Problem constants
#define B_SZ   4
#define C_IN   512
#define TD     512
#define HW     4096
#define HH     64
#define WW     64
#define NCH3   1536          // 3*td
#define GROUPS 192
#define NHEAD  128           // 3072/24
#define EPSF   1e-15f

// ---------------- scratch (static device globals; no runtime alloc) ----------------
__device__ float g_qkv [(long)B_SZ * NCH3 * HW];   // 25,165,824 floats
__device__ float g_agg [(long)B_SZ * NCH3 * HW];
__device__ float g_outn[(long)B_SZ * 1024 * HW];   // normalized attention output
__device__ float g_vk  [B_SZ * NHEAD * 72];        // 9x8 per (b,head)

// ---------------- tf32 mma helpers ----------------
__device__ __forceinline__ uint32_t f2tf32(float f) {
    uint32_t r; asm("cvt.rna.tf32.f32 %0, %1;" : "=r"(r) : "f"(f)); return r;
}
__device__ __forceinline__ void mma_tf32(float (&c)[4], const uint32_t (&a)[4], const uint32_t (&b)[2]) {
    asm volatile(
        "mma.sync.aligned.m16n8k8.row.col.f32.tf32.tf32.f32 "
        "{%0,%1,%2,%3}, {%4,%5,%6,%7}, {%8,%9}, {%0,%1,%2,%3};\n"
        : "+f"(c[0]), "+f"(c[1]), "+f"(c[2]), "+f"(c[3])
        : "r"(a[0]), "r"(a[1]), "r"(a[2]), "r"(a[3]), "r"(b[0]), "r"(b[1]));
}

// ---------------- GEMM: C[b] = W[M,K] * X[b][K,N] (+ optional addend), tf32 ----------------
// BM=128, BN=64, BK=16; 256 threads = 8 warps (4x2), warp tile 32x32.
#define GBM 128
#define GBN 64
#define GBK 16

__global__ void __launch_bounds__(256)
gemm_tf32_kernel(const float* __restrict__ Wm, const float* __restrict__ Xm,
                 float* __restrict__ Cm, const float* __restrict__ Addend,
                 int M, int K, int N)
{
    int b  = blockIdx.z;
    const float* Xb = Xm + (long)b * K * N;
    float*       Cb = Cm + (long)b * M * N;
    const float* Ab = Addend ? (Addend + (long)b * M * N) : nullptr;

    int m0 = blockIdx.y * GBM;
    int n0 = blockIdx.x * GBN;

    __shared__ float As[GBK][GBM + 8];   // k-major, padded: conflict-free frag loads
    __shared__ float Bs[GBK][GBN + 8];

    int tid  = threadIdx.x;
    int lane = tid & 31, warp = tid >> 5;
    int wm = warp >> 1, wn = warp & 1;
    int g = lane >> 2, t = lane & 3;

    float acc[2][4][4];
#pragma unroll
    for (int i = 0; i < 2; i++)
#pragma unroll
        for (int j = 0; j < 4; j++)
#pragma unroll
            for (int q = 0; q < 4; q++) acc[i][j][q] = 0.f;

    for (int kk = 0; kk < K; kk += GBK) {
        // Load A tile: W[m0+m][kk + k], transposed into As[k][m]
#pragma unroll
        for (int r = 0; r < 2; r++) {
            int idx = tid + r * 256;          // 0..511
            int m   = idx >> 2;
            int kq  = (idx & 3) * 4;
            float4 v = *(const float4*)&Wm[(long)(m0 + m) * K + kk + kq];
            As[kq + 0][m] = v.x; As[kq + 1][m] = v.y;
            As[kq + 2][m] = v.z; As[kq + 3][m] = v.w;
        }
        // Load B tile: X[kk+k][n0+n]
        {
            int k  = tid >> 4;
            int nf = (tid & 15) * 4;
            float4 v = *(const float4*)&Xb[(long)(kk + k) * N + n0 + nf];
            *(float4*)&Bs[k][nf] = v;
        }
        __syncthreads();

#pragma unroll
        for (int k8 = 0; k8 < GBK; k8 += 8) {
            uint32_t af[2][4], bf[4][2];
#pragma unroll
            for (int mt = 0; mt < 2; mt++) {
                int mr = wm * 32 + mt * 16 + g;
                af[mt][0] = f2tf32(As[k8 + t    ][mr    ]);
                af[mt][1] = f2tf32(As[k8 + t    ][mr + 8]);
                af[mt][2] = f2tf32(As[k8 + t + 4][mr    ]);
                af[mt][3] = f2tf32(As[k8 + t + 4][mr + 8]);
            }
#pragma unroll
            for (int nt = 0; nt < 4; nt++) {
                int nc = wn * 32 + nt * 8 + g;
                bf[nt][0] = f2tf32(Bs[k8 + t    ][nc]);
                bf[nt][1] = f2tf32(Bs[k8 + t + 4][nc]);
            }
#pragma unroll
            for (int mt = 0; mt < 2; mt++)
#pragma unroll
                for (int nt = 0; nt < 4; nt++)
                    mma_tf32(acc[mt][nt], af[mt], bf[nt]);
        }
        __syncthreads();
    }

    // Epilogue
#pragma unroll
    for (int mt = 0; mt < 2; mt++) {
#pragma unroll
        for (int nt = 0; nt < 4; nt++) {
            int row = m0 + wm * 32 + mt * 16 + g;
            int col = n0 + wn * 32 + nt * 8 + 2 * t;
            float2 v0 = make_float2(acc[mt][nt][0], acc[mt][nt][1]);
            float2 v1 = make_float2(acc[mt][nt][2], acc[mt][nt][3]);
            long o0 = (long)row * N + col;
            long o1 = (long)(row + 8) * N + col;
            if (Ab) {
                float2 a0 = *(const float2*)&Ab[o0];
                float2 a1 = *(const float2*)&Ab[o1];
                v0.x += a0.x; v0.y += a0.y;
                v1.x += a1.x; v1.y += a1.y;
            }
            *(float2*)&Cb[o0] = v0;
            *(float2*)&Cb[o1] = v1;
        }
    }
}

// ---------------- fused depthwise 5x5 + grouped pointwise 8x8 ----------------
// grid: (4 spatial tiles of 32x32, 192 groups, 4 batch); 256 threads.
__global__ void __launch_bounds__(256)
dwpw_kernel(const float* __restrict__ qkv, const float* __restrict__ w_dw,
            const float* __restrict__ w_pw, float* __restrict__ agg)
{
    __shared__ float in_s[36][36];
    __shared__ float dw_s[8][1024];
    __shared__ float wpw_s[64];

    int tid = threadIdx.x;
    int tb  = blockIdx.x;            // 0..3
    int x0  = (tb & 1) * 32;
    int y0  = (tb >> 1) * 32;
    int grp = blockIdx.y;
    int b   = blockIdx.z;

    if (tid < 64) wpw_s[tid] = w_pw[(grp * 8 + (tid >> 3)) * 8 + (tid & 7)];

    for (int c = 0; c < 8; c++) {
        int ch = grp * 8 + c;
        const float* src = qkv + ((long)b * NCH3 + ch) * HW;
        __syncthreads();                       // protect in_s reuse
        for (int i = tid; i < 36 * 36; i += 256) {
            int r = i / 36, cc = i % 36;
            int gy = y0 + r - 2, gx = x0 + cc - 2;
            float v = 0.f;
            if (gy >= 0 && gy < HH && gx >= 0 && gx < WW)
                v = src[gy * WW + gx];
            in_s[r][cc] = v;
        }
        float wreg[25];
#pragma unroll
        for (int j = 0; j < 25; j++) wreg[j] = __ldg(&w_dw[ch * 25 + j]);
        __syncthreads();
        for (int p = tid; p < 1024; p += 256) {
            int py = p >> 5, px = p & 31;
            float s = 0.f;
#pragma unroll
            for (int dy = 0; dy < 5; dy++)
#pragma unroll
                for (int dx = 0; dx < 5; dx++)
                    s += in_s[py + dy][px + dx] * wreg[dy * 5 + dx];
            dw_s[c][p] = s;
        }
    }
    __syncthreads();

    // pointwise 8->8 within group
    for (int p = tid; p < 1024; p += 256) {
        float din[8];
#pragma unroll
        for (int i = 0; i < 8; i++) din[i] = dw_s[i][p];
        int py = p >> 5, px = p & 31;
        long base = ((long)b * NCH3 + grp * 8) * HW + (long)(y0 + py) * WW + (x0 + px);
#pragma unroll
        for (int o = 0; o < 8; o++) {
            float s = 0.f;
#pragma unroll
            for (int i = 0; i < 8; i++) s += wpw_s[o * 8 + i] * din[i];
            agg[base + (long)o * HW] = s;
        }
    }
}

// ---------------- vk reduction: vk[b,h] (9x8) = sum_n v(d,n) k(e,n) ----------------
__global__ void __launch_bounds__(256)
vk_kernel(const float* __restrict__ qkv, const float* __restrict__ agg,
          float* __restrict__ vkout)
{
    int bh = blockIdx.x;
    int b = bh >> 7, h = bh & 127;
    const float* src = (h < 64)
        ? qkv + ((long)b * NCH3 + h * 24) * HW
        : agg + ((long)b * NCH3 + (h - 64) * 24) * HW;

    int tid = threadIdx.x, lane = tid & 31;
    float acc[72];
#pragma unroll
    for (int i = 0; i < 72; i++) acc[i] = 0.f;

    for (int n = tid; n < HW; n += 256) {
        float kv[8], vv[8];
#pragma unroll
        for (int e = 0; e < 8; e++) kv[e] = fmaxf(src[(long)(8 + e) * HW + n], 0.f);
#pragma unroll
        for (int d = 0; d < 8; d++) vv[d] = src[(long)(16 + d) * HW + n];
#pragma unroll
        for (int d = 0; d < 8; d++)
#pragma unroll
            for (int e = 0; e < 8; e++) acc[d * 8 + e] += vv[d] * kv[e];
#pragma unroll
        for (int e = 0; e < 8; e++) acc[64 + e] += kv[e];   // v row of ones
    }
    // warp reduce all 72
#pragma unroll
    for (int i = 0; i < 72; i++) {
#pragma unroll
        for (int off = 16; off > 0; off >>= 1)
            acc[i] += __shfl_xor_sync(0xFFFFFFFFu, acc[i], off);
    }
    __shared__ float red[72];
    if (tid < 72) red[tid] = 0.f;
    __syncthreads();
    if (lane == 0) {
#pragma unroll
        for (int i = 0; i < 72; i++) atomicAdd(&red[i], acc[i]);
    }
    __syncthreads();
    if (tid < 72) vkout[(long)bh * 72 + tid] = red[tid];
}

// ---------------- per-pixel attention output + normalization ----------------
// grid: (16 pixel chunks, 512 (b,h)); 256 threads.
__global__ void __launch_bounds__(256)
outnorm_kernel(const float* __restrict__ qkv, const float* __restrict__ agg,
               const float* __restrict__ vkin, float* __restrict__ outn)
{
    int bh = blockIdx.y;
    int b = bh >> 7, h = bh & 127;
    const float* src = (h < 64)
        ? qkv + ((long)b * NCH3 + h * 24) * HW
        : agg + ((long)b * NCH3 + (h - 64) * 24) * HW;

    __shared__ float vks[72];
    int tid = threadIdx.x;
    if (tid < 72) vks[tid] = vkin[(long)bh * 72 + tid];
    __syncthreads();

    int n = blockIdx.x * 256 + tid;
    float q[8];
#pragma unroll
    for (int e = 0; e < 8; e++) q[e] = fmaxf(src[(long)e * HW + n], 0.f);

    float den = 0.f;
#pragma unroll
    for (int e = 0; e < 8; e++) den += vks[64 + e] * q[e];
    float inv = 1.f / (den + EPSF);

    long obase = ((long)b * 1024 + h * 8) * HW + n;
#pragma unroll
    for (int d = 0; d < 8; d++) {
        float num = 0.f;
#pragma unroll
        for (int e = 0; e < 8; e++) num += vks[d * 8 + e] * q[e];
        outn[obase + (long)d * HW] = num * inv;
    }
}

// ---------------- launch ----------------
extern "C" void kernel_launch(void* const* d_in, const int* in_sizes, int n_in,
                              void* d_out, int out_size)
{
    const float* x      = (const float*)d_in[0];
    const float* w_qkv  = (const float*)d_in[1];
    const float* w_dw   = (const float*)d_in[2];
    const float* w_pw   = (const float*)d_in[3];
    const float* w_proj = (const float*)d_in[4];
    float* out = (float*)d_out;

    float *qkv_p, *agg_p, *outn_p, *vk_p;
    cudaGetSymbolAddress((void**)&qkv_p,  g_qkv);
    cudaGetSymbolAddress((void**)&agg_p,  g_agg);
    cudaGetSymbolAddress((void**)&outn_p, g_outn);
    cudaGetSymbolAddress((void**)&vk_p,   g_vk);

    // 1) qkv = W_qkv @ x   : M=1536, K=512, N=4096, per batch
    gemm_tf32_kernel<<<dim3(HW / GBN, NCH3 / GBM, B_SZ), 256>>>(
        w_qkv, x, qkv_p, nullptr, NCH3, C_IN, HW);

    // 2) agg = grouped_pw(depthwise5x5(qkv))
    dwpw_kernel<<<dim3(4, GROUPS, B_SZ), 256>>>(qkv_p, w_dw, w_pw, agg_p);

    // 3) vk[b,h] 9x8 reductions
    vk_kernel<<<B_SZ * NHEAD, 256>>>(qkv_p, agg_p, vk_p);

    // 4) normalized attention output
    outnorm_kernel<<<dim3(HW / 256, B_SZ * NHEAD), 256>>>(qkv_p, agg_p, vk_p, outn_p);

    // 5) out = x + W_proj @ outn : M=512, K=1024, N=4096, per batch
    gemm_tf32_kernel<<<dim3(HW / GBN, 512 / GBM, B_SZ), 256>>>(
        w_proj, outn_p, out, x, 512, 1024, HW);
}